// round 17
// baseline (speedup 1.0000x reference)
#include <cuda_runtime.h>
#include <cuda_fp16.h>
#include <cstdint>

// ---------------------------------------------------------------------------
// Problem constants
// ---------------------------------------------------------------------------
constexpr int BATCH = 4;
constexpr int SEQ   = 2048;
constexpr int DIM   = 1024;
constexpr int MTOT  = BATCH * SEQ;   // 8192
constexpr int NTILES = SEQ / 128;    // 16 n-tiles per row

// ---------------------------------------------------------------------------
// Static device scratch (zero-initialized; strictly-upper region of
// g_ph / g_spart is never written and must stay zero)
// ---------------------------------------------------------------------------
__device__ __half g_xh[(size_t)MTOT * DIM];
__device__ __half g_wh[(size_t)3 * DIM * DIM];
__device__ __half g_qh[(size_t)MTOT * DIM];
__device__ __half g_kh[(size_t)MTOT * DIM];
__device__ __half g_vh[(size_t)MTOT * DIM];
__device__ __half g_ph[(size_t)BATCH * SEQ * SEQ];   // exp(scores), unnormalized
__device__ float  g_spart[(size_t)MTOT * NTILES];    // per-tile partial row sums
__device__ int    g_ctr;                             // global work-queue counter
__device__ int    g_done;                            // CTA completion counter
__device__ int    g_xflag[64], g_wflag[24];          // conversion done (4 = ready)
__device__ int    g_qrow[64], g_krow[64], g_vrow[64];// completed n-tiles (8 = done)
__device__ int    g_srow[64];                        // completed scores tiles per row

// ---------------------------------------------------------------------------
// Tiling
// ---------------------------------------------------------------------------
constexpr int NTH = 256;                  // 8 warps: 2 (m) x 4 (n)
constexpr int ROWB_A  = 80;               // 32 fp16 = 64B + 16B pad (bank-safe)
constexpr int ATILE   = 128 * ROWB_A;     // 10240 B
constexpr int ROWB_V  = 272;              // 128 fp16 = 256B + 16B pad
constexpr int VTILE   = 32 * ROWB_V;      // 8704 B
constexpr int STAGE_PV = ATILE + VTILE;           // 18944
constexpr int STAGE_NT = 2 * ATILE;               // 20480
constexpr int SMEM_ALL = 4 * STAGE_NT;            // 81920

constexpr int N_CONV  = 352;                      // 256 x-chunks + 96 w-chunks
constexpr int N_QKV   = 1536;                     // Q,K,V x 8 x 64
constexpr int N_SCORE = 544;                      // 136 x 4
constexpr int N_PV    = 512;                      // 16 x 8 x 4
constexpr int N_ITEMS = N_CONV + N_QKV + N_SCORE + N_PV;   // 2944
constexpr int GRID_P  = 296;                      // 148 SMs x occ-2

// ---------------------------------------------------------------------------
// PTX helpers (base sm_103-legal only: cp.async, ldmatrix, mma.sync)
// ---------------------------------------------------------------------------
__device__ __forceinline__ uint32_t smem_u32(const void* p) {
    uint32_t a;
    asm("{ .reg .u64 t; cvta.to.shared.u64 t, %1; cvt.u32.u64 %0, t; }"
        : "=r"(a) : "l"(p));
    return a;
}
#define CP16(dst, src) \
    asm volatile("cp.async.cg.shared.global [%0], [%1], 16;" :: "r"(dst), "l"(src))
#define CP_COMMIT() asm volatile("cp.async.commit_group;" ::: "memory")
#define CP_WAIT0()  asm volatile("cp.async.wait_group 0;" ::: "memory")
#define CP_WAIT1()  asm volatile("cp.async.wait_group 1;" ::: "memory")
#define CP_WAIT2()  asm volatile("cp.async.wait_group 2;" ::: "memory")
#define NSLEEP()    asm volatile("nanosleep.u32 200;")

#define LDSM4(r, a) asm volatile( \
    "ldmatrix.sync.aligned.m8n8.x4.shared.b16 {%0,%1,%2,%3}, [%4];" \
    : "=r"((r)[0]), "=r"((r)[1]), "=r"((r)[2]), "=r"((r)[3]) : "r"(a))
#define LDSM4T(r, a) asm volatile( \
    "ldmatrix.sync.aligned.m8n8.x4.trans.shared.b16 {%0,%1,%2,%3}, [%4];" \
    : "=r"((r)[0]), "=r"((r)[1]), "=r"((r)[2]), "=r"((r)[3]) : "r"(a))

__device__ __forceinline__ void mma_f16(float* d, const uint32_t* a, const uint32_t* b) {
    asm volatile(
        "mma.sync.aligned.m16n8k16.row.col.f32.f16.f16.f32 "
        "{%0,%1,%2,%3}, {%4,%5,%6,%7}, {%8,%9}, {%0,%1,%2,%3};"
        : "+f"(d[0]), "+f"(d[1]), "+f"(d[2]), "+f"(d[3])
        : "r"(a[0]), "r"(a[1]), "r"(a[2]), "r"(a[3]), "r"(b[0]), "r"(b[1]));
}

// ---------------------------------------------------------------------------
// Stage loaders (256 threads)
// ---------------------------------------------------------------------------
__device__ __forceinline__ void load_nt(uint32_t sdst, const __half* src,
                                        int ld, int kt) {
    const int tid = threadIdx.x;
    #pragma unroll
    for (int it = 0; it < 2; ++it) {
        int idx = it * NTH + tid;
        int row = idx >> 2, seg = idx & 3;
        CP16(sdst + row * ROWB_A + seg * 16,
             src + (size_t)row * ld + kt + seg * 8);
    }
}
__device__ __forceinline__ void load_v(uint32_t sdst, const __half* src, int kt) {
    const int tid = threadIdx.x;
    #pragma unroll
    for (int it = 0; it < 2; ++it) {
        int idx = it * NTH + tid;
        int row = idx >> 4, seg = idx & 15;
        CP16(sdst + row * ROWB_V + seg * 16,
             src + (size_t)(kt + row) * DIM + seg * 8);
    }
}
__device__ __forceinline__ void load_stage_nt(uint32_t st,
    const __half* Ah, int lda, const __half* Bh, int ldb, int kt)
{
    load_nt(st, Ah, lda, kt);
    load_nt(st + ATILE, Bh, ldb, kt);
    CP_COMMIT();
}
__device__ __forceinline__ void load_stage_pv(uint32_t st,
    const __half* Ah, const __half* Vh, int kt)
{
    load_nt(st, Ah, SEQ, kt);
    load_v(st + ATILE, Vh, kt);
    CP_COMMIT();
}

// ---------------------------------------------------------------------------
// NT mainloop (4-stage, LDSM x4 B-pairs). nstages >= 3.
// ---------------------------------------------------------------------------
__device__ __forceinline__ void mainloop_nt(
    const __half* Ah, int lda, const __half* Bh, int ldb,
    int nstages, char* smem, float (&acc)[4][4][4])
{
    const int lane = threadIdx.x & 31, wid = threadIdx.x >> 5;
    const int wm = (wid >> 2) * 64, wn = (wid & 3) * 32;
    const uint32_t sb = smem_u32(smem);
    const uint32_t aoff = (lane & 15) * ROWB_A + (lane >> 4) * 16;
    const uint32_t boff = (lane & 7) * ROWB_A + ((lane >> 3) & 1) * 16
                        + (lane >> 4) * (8 * ROWB_A);

    load_stage_nt(sb,                Ah, lda, Bh, ldb, 0);
    load_stage_nt(sb + STAGE_NT,     Ah, lda, Bh, ldb, 32);
    load_stage_nt(sb + 2 * STAGE_NT, Ah, lda, Bh, ldb, 64);

    for (int s = 0; s < nstages; ++s) {
        const int rem = nstages - s;
        if (rem >= 3) { CP_WAIT2(); } else if (rem == 2) { CP_WAIT1(); } else { CP_WAIT0(); }
        __syncthreads();
        if (s + 3 < nstages)
            load_stage_nt(sb + ((s + 3) & 3) * STAGE_NT,
                          Ah, lda, Bh, ldb, (s + 3) * 32);

        const uint32_t st = sb + (s & 3) * STAGE_NT;
        #pragma unroll
        for (int k16 = 0; k16 < 2; ++k16) {
            uint32_t ah[4][4], bh[4][2];
            #pragma unroll
            for (int mb = 0; mb < 4; ++mb) {
                uint32_t ad = st + (wm + mb * 16) * ROWB_A + k16 * 32 + aoff;
                LDSM4(ah[mb], ad);
            }
            #pragma unroll
            for (int nb = 0; nb < 4; nb += 2) {
                uint32_t bd = st + ATILE + (wn + nb * 8) * ROWB_A + k16 * 32 + boff;
                uint32_t r[4];
                LDSM4(r, bd);
                bh[nb][0] = r[0]; bh[nb][1] = r[1];
                bh[nb + 1][0] = r[2]; bh[nb + 1][1] = r[3];
            }
            #pragma unroll
            for (int mb = 0; mb < 4; ++mb)
                #pragma unroll
                for (int nb = 0; nb < 4; ++nb)
                    mma_f16(acc[mb][nb], ah[mb], bh[nb]);
        }
    }
    __syncthreads();
}

// ---------------------------------------------------------------------------
// PV mainloop (4-stage, x4 trans V-pairs). nstages >= 4.
// ---------------------------------------------------------------------------
__device__ __forceinline__ void mainloop_pv(
    const __half* Ah, const __half* Vh,
    int nstages, char* smem, float (&acc)[4][4][4])
{
    const int lane = threadIdx.x & 31, wid = threadIdx.x >> 5;
    const int wm = (wid >> 2) * 64, wn = (wid & 3) * 32;
    const uint32_t sb = smem_u32(smem);
    const uint32_t aoff  = (lane & 15) * ROWB_A + (lane >> 4) * 16;
    const uint32_t boffv = ((lane & 7) + ((lane >> 3) & 1) * 8) * ROWB_V
                         + (lane >> 4) * 16;

    load_stage_pv(sb,                Ah, Vh, 0);
    load_stage_pv(sb + STAGE_PV,     Ah, Vh, 32);
    load_stage_pv(sb + 2 * STAGE_PV, Ah, Vh, 64);

    for (int s = 0; s < nstages; ++s) {
        const int rem = nstages - s;
        if (rem >= 3) { CP_WAIT2(); } else if (rem == 2) { CP_WAIT1(); } else { CP_WAIT0(); }
        __syncthreads();
        if (s + 3 < nstages)
            load_stage_pv(sb + ((s + 3) & 3) * STAGE_PV, Ah, Vh, (s + 3) * 32);

        const uint32_t st = sb + (s & 3) * STAGE_PV;
        #pragma unroll
        for (int k16 = 0; k16 < 2; ++k16) {
            uint32_t ah[4][4], bh[4][2];
            #pragma unroll
            for (int mb = 0; mb < 4; ++mb) {
                uint32_t ad = st + (wm + mb * 16) * ROWB_A + k16 * 32 + aoff;
                LDSM4(ah[mb], ad);
            }
            #pragma unroll
            for (int nb = 0; nb < 4; nb += 2) {
                uint32_t bd = st + ATILE + k16 * 16 * ROWB_V + boffv + (wn + nb * 8) * 2;
                uint32_t r[4];
                LDSM4T(r, bd);
                bh[nb][0] = r[0]; bh[nb][1] = r[1];
                bh[nb + 1][0] = r[2]; bh[nb + 1][1] = r[3];
            }
            #pragma unroll
            for (int mb = 0; mb < 4; ++mb)
                #pragma unroll
                for (int nb = 0; nb < 4; ++nb)
                    mma_f16(acc[mb][nb], ah[mb], bh[nb]);
        }
    }
    __syncthreads();
}

// ---------------------------------------------------------------------------
// Spin helper: tid0 waits for *flag >= need.
// ---------------------------------------------------------------------------
__device__ __forceinline__ void wait_flag(const int* flag, int need) {
    if (threadIdx.x == 0) {
        while (*(volatile const int*)flag < need) NSLEEP();
    }
}

// ---------------------------------------------------------------------------
// Fused persistent kernel. Work queue:
//   [0,256)       x->fp16 chunks (32 rows each; 4 per 128-row tile)
//   [256,352)     w->fp16 chunks (32 rows each; 4 per 128-row block, 3 z)
//   [352,864)     Q tiles, rows my-desc
//   [864,1376)    K tiles
//   [1376,1888)   V tiles
//   [1888,2432)   scores (triangular, my-desc)
//   [2432,2944)   PV (my-desc)
// Per-tile math identical to the split kernels -> bitwise-identical output.
// Last CTA to finish resets all queue state for the next graph replay.
// ---------------------------------------------------------------------------
__global__ __launch_bounds__(NTH, 2)
void fused_attn(float* __restrict__ out,
                const float* __restrict__ x,
                const float* __restrict__ wq,
                const float* __restrict__ wk,
                const float* __restrict__ wv)
{
    extern __shared__ char smem[];
    __shared__ int s_t;
    const int lane = threadIdx.x & 31, wid = threadIdx.x >> 5;
    const int wm = (wid >> 2) * 64, wn = (wid & 3) * 32;

    for (;;) {
        if (threadIdx.x == 0) s_t = atomicAdd(&g_ctr, 1);
        __syncthreads();
        const int t = s_t;
        if (t >= N_ITEMS) break;

        if (t < N_CONV) {
            // ---------------- conversion chunk (32 rows x 1024 cols) ----------
            const float* src;
            __half* dst;
            int* flag;
            if (t < 256) {
                src = x + (size_t)t * 32 * DIM;
                dst = g_xh + (size_t)t * 32 * DIM;
                flag = &g_xflag[t >> 2];
            } else {
                const int j = t - 256;          // 0..95
                const int z = j >> 5, c = j & 31;
                const float* w = (z == 0) ? wq : (z == 1) ? wk : wv;
                src = w + (size_t)c * 32 * DIM;
                dst = g_wh + (size_t)z * DIM * DIM + (size_t)c * 32 * DIM;
                flag = &g_wflag[z * 8 + (c >> 2)];
            }
            const float4* s4 = reinterpret_cast<const float4*>(src);
            #pragma unroll 8
            for (int i = threadIdx.x; i < 32 * DIM / 4; i += NTH) {
                float4 v = s4[i];
                __half2 h01 = __floats2half2_rn(v.x, v.y);
                __half2 h23 = __floats2half2_rn(v.z, v.w);
                *reinterpret_cast<__half2*>(dst + i * 4)     = h01;
                *reinterpret_cast<__half2*>(dst + i * 4 + 2) = h23;
            }
            __threadfence();
            __syncthreads();
            if (threadIdx.x == 0) atomicAdd(flag, 1);
        } else if (t < N_CONV + N_QKV) {
            // ---------------- QKV tile ----------------
            const int tt  = t - N_CONV;
            const int z   = tt >> 9;                   // 0:Q 1:K 2:V
            const int sub = tt & 511;
            const int n0  = (sub & 7) * 128;
            const int nx  = sub & 7;
            const int rowidx = sub >> 3;               // 0..63
            const int b   = rowidx >> 4;
            const int my  = 15 - (rowidx & 15);        // descending
            const int r   = b * 16 + my;
            const int m0  = r * 128;

            wait_flag(&g_xflag[r], 4);
            wait_flag(&g_wflag[z * 8 + nx], 4);
            __syncthreads();
            __threadfence();

            float acc[4][4][4];
            #pragma unroll
            for (int i = 0; i < 4; ++i)
                #pragma unroll
                for (int j = 0; j < 4; ++j)
                    #pragma unroll
                    for (int q = 0; q < 4; ++q) acc[i][j][q] = 0.f;

            mainloop_nt(g_xh + (size_t)m0 * DIM, DIM,
                        g_wh + (size_t)z * DIM * DIM + (size_t)n0 * DIM, DIM,
                        DIM / 32, smem, acc);

            const float scale = (z == 0) ? 0.03125f : 1.0f;
            __half* dh = (z == 0) ? g_qh : (z == 1) ? g_kh : g_vh;
            #pragma unroll
            for (int mb = 0; mb < 4; ++mb)
                #pragma unroll
                for (int rh = 0; rh < 2; ++rh) {
                    const int row = m0 + wm + mb * 16 + (lane >> 2) + rh * 8;
                    #pragma unroll
                    for (int nb = 0; nb < 4; ++nb) {
                        const int col = n0 + wn + nb * 8 + (lane & 3) * 2;
                        __half h0 = __float2half_rn(acc[mb][nb][rh * 2 + 0] * scale);
                        __half h1 = __float2half_rn(acc[mb][nb][rh * 2 + 1] * scale);
                        *(uint32_t*)(dh + (size_t)row * DIM + col) =
                            (uint32_t)__half_as_ushort(h0) |
                            ((uint32_t)__half_as_ushort(h1) << 16);
                    }
                }
            __threadfence();
            __syncthreads();
            if (threadIdx.x == 0) {
                int* fl = (z == 0) ? g_qrow : (z == 1) ? g_krow : g_vrow;
                atomicAdd(&fl[r], 1);
            }
        } else if (t < N_CONV + N_QKV + N_SCORE) {
            // ---------------- scores tile ----------------
            const int id  = t - N_CONV - N_QKV;
            const int b   = id & 3;
            const int rev = 135 - (id >> 2);
            int my = (int)((sqrtf(8.0f * rev + 1.0f) - 1.0f) * 0.5f);
            while ((my + 1) * (my + 2) / 2 <= rev) ++my;
            while (my * (my + 1) / 2 > rev) --my;
            const int nx = rev - my * (my + 1) / 2;
            const int m0 = my * 128;
            const int n0 = nx * 128;

            wait_flag(&g_qrow[b * 16 + my], 8);
            wait_flag(&g_krow[b * 16 + nx], 8);
            __syncthreads();
            __threadfence();

            float acc[4][4][4];
            #pragma unroll
            for (int i = 0; i < 4; ++i)
                #pragma unroll
                for (int j = 0; j < 4; ++j)
                    #pragma unroll
                    for (int q = 0; q < 4; ++q) acc[i][j][q] = 0.f;

            const size_t rowbase = (size_t)b * SEQ * DIM;
            mainloop_nt(g_qh + rowbase + (size_t)m0 * DIM, DIM,
                        g_kh + rowbase + (size_t)n0 * DIM, DIM,
                        DIM / 32, smem, acc);

            float (*ssum)[4] = reinterpret_cast<float (*)[4]>(smem);
            __half* dst = g_ph + (size_t)b * SEQ * SEQ;
            const bool diag = (n0 == m0);
            #pragma unroll
            for (int mb = 0; mb < 4; ++mb)
                #pragma unroll
                for (int rh = 0; rh < 2; ++rh) {
                    const int rloc = wm + mb * 16 + (lane >> 2) + rh * 8;
                    const int row  = m0 + rloc;
                    float rsum = 0.f;
                    #pragma unroll
                    for (int nb = 0; nb < 4; ++nb) {
                        const int col = n0 + wn + nb * 8 + (lane & 3) * 2;
                        float p0 = (!diag || col     <= row) ? __expf(acc[mb][nb][rh * 2 + 0]) : 0.f;
                        float p1 = (!diag || col + 1 <= row) ? __expf(acc[mb][nb][rh * 2 + 1]) : 0.f;
                        __half h0 = __float2half_rn(p0);
                        __half h1 = __float2half_rn(p1);
                        rsum += __half2float(h0) + __half2float(h1);
                        *(uint32_t*)(dst + (size_t)row * SEQ + col) =
                            (uint32_t)__half_as_ushort(h0) |
                            ((uint32_t)__half_as_ushort(h1) << 16);
                    }
                    rsum += __shfl_xor_sync(0xffffffffu, rsum, 1);
                    rsum += __shfl_xor_sync(0xffffffffu, rsum, 2);
                    if ((lane & 3) == 0) ssum[rloc][wid & 3] = rsum;
                }
            __syncthreads();
            if (threadIdx.x < 128) {
                const int rloc = threadIdx.x;
                float s = ssum[rloc][0] + ssum[rloc][1] + ssum[rloc][2] + ssum[rloc][3];
                g_spart[((size_t)b * SEQ + m0 + rloc) * NTILES + nx] = s;
            }
            __threadfence();
            __syncthreads();
            if (threadIdx.x == 0) atomicAdd(&g_srow[b * 16 + my], 1);
        } else {
            // ---------------- PV tile ----------------
            const int id  = t - N_CONV - N_QKV - N_SCORE;
            const int my  = 15 - (id >> 5);            // longest K first
            const int sub = id & 31;
            const int n0  = (sub & 7) * 128;
            const int b   = sub >> 3;
            const int m0  = my * 128;

            wait_flag(&g_srow[b * 16 + my], my + 1);
            if (threadIdx.x == 0) {
                for (int j = 0; j <= my; ++j)
                    while (*(volatile const int*)&g_vrow[b * 16 + j] < 8) NSLEEP();
            }
            __syncthreads();
            __threadfence();

            float acc[4][4][4];
            #pragma unroll
            for (int i = 0; i < 4; ++i)
                #pragma unroll
                for (int j = 0; j < 4; ++j)
                    #pragma unroll
                    for (int q = 0; q < 4; ++q) acc[i][j][q] = 0.f;

            mainloop_pv(g_ph + (size_t)b * SEQ * SEQ + (size_t)m0 * SEQ,
                        g_vh + (size_t)b * SEQ * DIM + n0,
                        (m0 + 128) / 32, smem, acc);

            float* sinv = reinterpret_cast<float*>(smem);
            if (threadIdx.x < 128) {
                const float* p = g_spart + ((size_t)b * SEQ + m0 + threadIdx.x) * NTILES;
                float s = 0.f;
                #pragma unroll
                for (int tt = 0; tt < NTILES; ++tt) s += __ldcg(p + tt);
                sinv[threadIdx.x] = 1.0f / s;
            }
            __syncthreads();

            float* dst = out + (size_t)b * SEQ * DIM;
            #pragma unroll
            for (int mb = 0; mb < 4; ++mb)
                #pragma unroll
                for (int rh = 0; rh < 2; ++rh) {
                    const int rloc = wm + mb * 16 + (lane >> 2) + rh * 8;
                    const int row  = m0 + rloc;
                    const float inv = sinv[rloc];
                    #pragma unroll
                    for (int nb = 0; nb < 4; ++nb) {
                        const int col = n0 + wn + nb * 8 + (lane & 3) * 2;
                        *(float2*)(dst + (size_t)row * DIM + col) =
                            make_float2(acc[mb][nb][rh * 2] * inv,
                                        acc[mb][nb][rh * 2 + 1] * inv);
                    }
                }
        }
        __syncthreads();   // protect smem / s_t before next pop
    }

    // ---- self-reset for next graph replay: last CTA out restores state ----
    __threadfence();
    __syncthreads();
    if (threadIdx.x == 0) {
        int d = atomicAdd(&g_done, 1);
        if (d == GRID_P - 1) {
            g_ctr = 0;
            for (int i = 0; i < 64; ++i) {
                g_xflag[i] = 0; g_qrow[i] = 0; g_krow[i] = 0;
                g_vrow[i] = 0; g_srow[i] = 0;
            }
            for (int i = 0; i < 24; ++i) g_wflag[i] = 0;
            __threadfence();
            g_done = 0;
        }
    }
}

// ---------------------------------------------------------------------------
extern "C" void kernel_launch(void* const* d_in, const int* in_sizes, int n_in,
                              void* d_out, int out_size)
{
    const float* x  = (const float*)d_in[0];
    const float* wq = (const float*)d_in[1];
    const float* wk = (const float*)d_in[2];
    const float* wv = (const float*)d_in[3];
    float* out = (float*)d_out;

    cudaFuncSetAttribute(fused_attn, cudaFuncAttributeMaxDynamicSharedMemorySize, SMEM_ALL);
    fused_attn<<<GRID_P, NTH, SMEM_ALL>>>(out, x, wq, wk, wv);
}